// round 1
// baseline (speedup 1.0000x reference)
#include <cuda_runtime.h>

// DifferentiableJPEG on GB300:
//   x[32,512,512,3] fp32 -> y[32,512,512,3], Xq[32*3*4096,8,8]
// d_out = [ y | Xq ] fp32.
//
// 8 threads per 8x8 tile; each thread holds one row (all 3 channels).
// DCT/IDCT as row-ops with immediate coefficients; 2 smem transposes/channel
// (pad-9 layout, conflict-free); warp-local sync only.

static __device__ __forceinline__ float round_sin5(float u) {
    // u - sum_{k=1..5} ((-1)^{k+1}/(pi k)) sin(2 pi k u)
    // exact periodic range reduction: sin(2 pi k u) == sin(2 pi k r), r = u - round(u)
    float r  = u - rintf(u);                 // r in [-0.5, 0.5]
    float a  = 6.283185307179586f * r;       // |a| <= pi
    float s1, c1;
    __sincosf(a, &s1, &c1);
    float tc = 2.0f * c1;
    float s2 = tc * s1;                      // sin(2a)
    float s3 = fmaf(tc, s2, -s1);            // sin(3a)
    float s4 = fmaf(tc, s3, -s2);            // sin(4a)
    float s5 = fmaf(tc, s4, -s3);            // sin(5a)
    float S  = 0.3183098861837907f  * s1
             - 0.15915494309189535f * s2
             + 0.10610329539459689f * s3
             - 0.07957747154594767f * s4
             + 0.06366197723675814f * s5;
    return u - S;
}

__global__ __launch_bounds__(256, 2)
void jpeg_kernel(const float* __restrict__ x,
                 const float* __restrict__ q_luma,
                 const float* __restrict__ q_chroma,
                 float* __restrict__ y_out,
                 float* __restrict__ xq_out)
{
    // DCT matrix exactly as the reference defines it (4-decimal literals).
    static constexpr float F[8][8] = {
        { 0.3536f, 0.3536f, 0.3536f, 0.3536f, 0.3536f, 0.3536f, 0.3536f, 0.3536f},
        { 0.4904f, 0.4157f, 0.2778f, 0.0975f,-0.0975f,-0.2778f,-0.4157f,-0.4904f},
        { 0.4619f, 0.1913f,-0.1913f,-0.4619f,-0.4619f,-0.1913f, 0.1913f, 0.4619f},
        { 0.4157f,-0.0975f,-0.4904f,-0.2778f, 0.2778f, 0.4904f, 0.0975f,-0.4157f},
        { 0.3536f,-0.3536f,-0.3536f, 0.3536f, 0.3536f,-0.3536f,-0.3536f, 0.3536f},
        { 0.2778f,-0.4904f, 0.0975f, 0.4157f,-0.4157f,-0.0975f, 0.4904f,-0.2778f},
        { 0.1913f,-0.4619f, 0.4619f,-0.1913f,-0.1913f, 0.4619f,-0.4619f, 0.1913f},
        { 0.0975f,-0.2778f, 0.4157f,-0.4904f, 0.4904f,-0.4157f, 0.2778f,-0.0975f}
    };

    __shared__ float tb[32 * 72];            // 32 tiles/CTA, 8x8 pad-9

    const int t  = threadIdx.x >> 3;         // tile within CTA (0..31)
    const int r  = threadIdx.x & 7;          // row within tile
    const int tg = blockIdx.x * 32 + t;      // global tile id (0..131071)
    const int b   = tg >> 12;                // batch
    const int rem = tg & 4095;
    const int bh  = rem >> 6;                // tile row
    const int bw  = rem & 63;                // tile col

    float* sm = tb + t * 72;

    // Q columns for this thread's transposed orientation: Q[j][r]
    float ql[8], qc[8], rql[8], rqc[8];
#pragma unroll
    for (int j = 0; j < 8; j++) {
        ql[j]  = q_luma  [j * 8 + r];
        qc[j]  = q_chroma[j * 8 + r];
        rql[j] = 1.0f / ql[j];
        rqc[j] = 1.0f / qc[j];
    }

    // Load this row's 8 pixels x 3 channels (24 contiguous floats, 16B aligned)
    const int pix_off = (((b * 512 + bh * 8 + r) * 512) + bw * 8) * 3;
    float px[24];
    {
        const float4* xin4 = (const float4*)(x + pix_off);
#pragma unroll
        for (int v = 0; v < 6; v++) {
            float4 q4 = xin4[v];
            px[v*4+0] = q4.x; px[v*4+1] = q4.y; px[v*4+2] = q4.z; px[v*4+3] = q4.w;
        }
    }

    // RGB -> YCbCr, minus 127 (cF0 = [0,128,128] -> biases [-127, 1, 1])
    float yc0[8], yc1[8], yc2[8];
#pragma unroll
    for (int p = 0; p < 8; p++) {
        float R = 255.0f * px[3*p+0];
        float G = 255.0f * px[3*p+1];
        float Bv= 255.0f * px[3*p+2];
        yc0[p] = fmaf(0.299f,     R, fmaf( 0.587f,    G,  0.114f    * Bv)) - 127.0f;
        yc1[p] = fmaf(-0.168736f, R, fmaf(-0.331264f, G,  0.5f      * Bv)) + 1.0f;
        yc2[p] = fmaf(0.5f,       R, fmaf(-0.418688f, G, -0.081312f * Bv)) + 1.0f;
    }

    float ib0[8], ib1[8], ib2[8];

#pragma unroll
    for (int c = 0; c < 3; c++) {
        float a[8], o[8];
#pragma unroll
        for (int j = 0; j < 8; j++)
            a[j] = (c == 0) ? yc0[j] : ((c == 1) ? yc1[j] : yc2[j]);

        // S1: o = row * F^T      (o[l] = sum_k a[k] F[l][k])
#pragma unroll
        for (int l = 0; l < 8; l++) {
            float s = a[0] * F[l][0];
#pragma unroll
            for (int k = 1; k < 8; k++) s = fmaf(a[k], F[l][k], s);
            o[l] = s;
        }

        // transpose 1
#pragma unroll
        for (int j = 0; j < 8; j++) sm[r * 9 + j] = o[j];
        __syncwarp();
#pragma unroll
        for (int j = 0; j < 8; j++) a[j] = sm[j * 9 + r];
        __syncwarp();

        // S2: thread now holds column r of X = F B F^T  (o[j] = X[j][r])
#pragma unroll
        for (int l = 0; l < 8; l++) {
            float s = a[0] * F[l][0];
#pragma unroll
            for (int k = 1; k < 8; k++) s = fmaf(a[k], F[l][k], s);
            o[l] = s;
        }

        // Quantize + soft round; a[j] = Xq[j][r]
#pragma unroll
        for (int j = 0; j < 8; j++) {
            float q  = (c == 0) ? ql[j]  : qc[j];
            float rq = (c == 0) ? rql[j] : rqc[j];
            float u  = o[j] * rq;
            a[j] = round_sin5(u) * q;
        }

        // Store Xq (layout: ((b*3+c)*4096 + bh*64+bw)*64 + j*8 + r)
        {
            float* xqp = xq_out + ((size_t)((b * 3 + c) * 4096 + bh * 64 + bw) << 6) + r;
#pragma unroll
            for (int j = 0; j < 8; j++) xqp[j * 8] = a[j];
        }

        // S3: multiply by F on the right (o[l] = sum_k a[k] F[k][l])
#pragma unroll
        for (int l = 0; l < 8; l++) {
            float s = a[0] * F[0][l];
#pragma unroll
            for (int k = 1; k < 8; k++) s = fmaf(a[k], F[k][l], s);
            o[l] = s;
        }

        // transpose 2
#pragma unroll
        for (int j = 0; j < 8; j++) sm[r * 9 + j] = o[j];
        __syncwarp();
#pragma unroll
        for (int j = 0; j < 8; j++) a[j] = sm[j * 9 + r];
        __syncwarp();

        // S4: ib row r = (F^T Xq F)[r][l]
#pragma unroll
        for (int l = 0; l < 8; l++) {
            float s = a[0] * F[0][l];
#pragma unroll
            for (int k = 1; k < 8; k++) s = fmaf(a[k], F[k][l], s);
            if (c == 0) ib0[l] = s;
            else if (c == 1) ib1[l] = s;
            else ib2[l] = s;
        }
    }

    // YCbCr -> RGB, /255, clip
#pragma unroll
    for (int p = 0; p < 8; p++) {
        float Y  = ib0[p] + 127.0f;
        float Cb = ib1[p] + 127.0f;
        float Cr = ib2[p] + 127.0f;
        float R = fmaf(1.402f,  Cr, Y) + (-1.402f  * 128.0f);
        float G = fmaf(-0.344136f, Cb, fmaf(-0.714136f, Cr, Y)) + (1.058272f * 128.0f);
        float Bv= fmaf(1.772f,  Cb, Y) + (-1.772f  * 128.0f);
        px[3*p+0] = fminf(fmaxf(R * (1.0f/255.0f), 0.0f), 1.0f);
        px[3*p+1] = fminf(fmaxf(G * (1.0f/255.0f), 0.0f), 1.0f);
        px[3*p+2] = fminf(fmaxf(Bv * (1.0f/255.0f), 0.0f), 1.0f);
    }
    {
        float4* yo4 = (float4*)(y_out + pix_off);
#pragma unroll
        for (int v = 0; v < 6; v++) {
            float4 q4;
            q4.x = px[v*4+0]; q4.y = px[v*4+1]; q4.z = px[v*4+2]; q4.w = px[v*4+3];
            yo4[v] = q4;
        }
    }
}

extern "C" void kernel_launch(void* const* d_in, const int* in_sizes, int n_in,
                              void* d_out, int out_size)
{
    const float* x  = (const float*)d_in[0];
    const float* ql = (const float*)d_in[1];
    const float* qc = (const float*)d_in[2];

    float* y  = (float*)d_out;
    float* xq = (float*)d_out + (size_t)32 * 512 * 512 * 3;

    // 131072 tiles total, 32 tiles per 256-thread CTA
    jpeg_kernel<<<4096, 256>>>(x, ql, qc, y, xq);
}

// round 2
// speedup vs baseline: 1.2378x; 1.2378x over previous
#include <cuda_runtime.h>

// DifferentiableJPEG on GB300:
//   x[32,512,512,3] fp32 -> y[32,512,512,3], Xq[32*3*4096,8,8]
// d_out = [ y | Xq ] fp32.
//
// 8 threads per 8x8 tile, one row each, 3 channels per thread.
// Even/odd-symmetry DCT (36 ops vs 64), Q tables in smem (frees 32 regs),
// 3 CTAs/SM. Transposes via pad-9 smem (conflict-free), warp-sync only.

static __device__ __forceinline__ float round_sin5(float u) {
    // u - sum_{k=1..5} ((-1)^{k+1}/(pi k)) sin(2 pi k u)
    float r  = u - rintf(u);                 // exact periodic reduction
    float a  = 6.283185307179586f * r;       // |a| <= pi
    float s1, c1;
    __sincosf(a, &s1, &c1);
    float tc = 2.0f * c1;
    float s2 = tc * s1;
    float s3 = fmaf(tc, s2, -s1);
    float s4 = fmaf(tc, s3, -s2);
    float s5 = fmaf(tc, s4, -s3);
    float S  = 0.3183098861837907f  * s1
             - 0.15915494309189535f * s2
             + 0.10610329539459689f * s3
             - 0.07957747154594767f * s4
             + 0.06366197723675814f * s5;
    return u - S;
}

// o[l] = sum_k a[k] * F[l][k]   (even/odd split, 36 ops)
static __device__ __forceinline__ void fdct8(const float a[8], float o[8]) {
    float e0 = a[0] + a[7], e1 = a[1] + a[6], e2 = a[2] + a[5], e3 = a[3] + a[4];
    float d0 = a[0] - a[7], d1 = a[1] - a[6], d2 = a[2] - a[5], d3 = a[3] - a[4];
    float g0 = e0 + e3, g1 = e1 + e2, g2 = e0 - e3, g3 = e1 - e2;
    o[0] = 0.3536f * (g0 + g1);
    o[4] = 0.3536f * (g0 - g1);
    o[2] = fmaf( 0.4619f, g2,  0.1913f * g3);
    o[6] = fmaf(-0.4619f, g3,  0.1913f * g2);
    o[1] = fmaf(0.4904f, d0, fmaf( 0.4157f, d1, fmaf( 0.2778f, d2,  0.0975f * d3)));
    o[3] = fmaf(0.4157f, d0, fmaf(-0.0975f, d1, fmaf(-0.4904f, d2, -0.2778f * d3)));
    o[5] = fmaf(0.2778f, d0, fmaf(-0.4904f, d1, fmaf( 0.0975f, d2,  0.4157f * d3)));
    o[7] = fmaf(0.0975f, d0, fmaf(-0.2778f, d1, fmaf( 0.4157f, d2, -0.4904f * d3)));
}

// o[l] = sum_k a[k] * F[k][l]   (even/odd split, 36 ops)
static __device__ __forceinline__ void idct8(const float a[8], float o[8]) {
    float t0 = 0.3536f * (a[0] + a[4]);
    float t1 = 0.3536f * (a[0] - a[4]);
    float u0 = fmaf(0.4619f, a[2],  0.1913f * a[6]);
    float u1 = fmaf(0.1913f, a[2], -0.4619f * a[6]);
    float E0 = t0 + u0, E1 = t1 + u1, E2 = t1 - u1, E3 = t0 - u0;
    float D0 = fmaf(0.4904f, a[1], fmaf( 0.4157f, a[3], fmaf( 0.2778f, a[5],  0.0975f * a[7])));
    float D1 = fmaf(0.4157f, a[1], fmaf(-0.0975f, a[3], fmaf(-0.4904f, a[5], -0.2778f * a[7])));
    float D2 = fmaf(0.2778f, a[1], fmaf(-0.4904f, a[3], fmaf( 0.0975f, a[5],  0.4157f * a[7])));
    float D3 = fmaf(0.0975f, a[1], fmaf(-0.2778f, a[3], fmaf( 0.4157f, a[5], -0.4904f * a[7])));
    o[0] = E0 + D0;  o[7] = E0 - D0;
    o[1] = E1 + D1;  o[6] = E1 - D1;
    o[2] = E2 + D2;  o[5] = E2 - D2;
    o[3] = E3 + D3;  o[4] = E3 - D3;
}

__global__ __launch_bounds__(256, 3)
void jpeg_kernel(const float* __restrict__ x,
                 const float* __restrict__ q_luma,
                 const float* __restrict__ q_chroma,
                 float* __restrict__ y_out,
                 float* __restrict__ xq_out)
{
    __shared__ float tb[32 * 72];   // 32 tiles/CTA, 8x8 pad-9 transpose buffers
    __shared__ float smq[128];      // [0:64) luma Q, [64:128) chroma Q
    __shared__ float smr[128];      // reciprocals

    // one-time Q table staging
    if (threadIdx.x < 128) {
        int c = threadIdx.x >> 6, i = threadIdx.x & 63;
        float q = c ? q_chroma[i] : q_luma[i];
        smq[threadIdx.x] = q;
        smr[threadIdx.x] = 1.0f / q;
    }
    __syncthreads();

    const int t  = threadIdx.x >> 3;          // tile within CTA
    const int r  = threadIdx.x & 7;           // row within tile
    const int tg = blockIdx.x * 32 + t;       // global tile id
    const int b   = tg >> 12;
    const int rem = tg & 4095;
    const int bh  = rem >> 6;
    const int bw  = rem & 63;

    float* sm = tb + t * 72;

    // load this row: 8 pixels x RGB = 24 contiguous floats
    const int pix_off = (((b * 512 + bh * 8 + r) * 512) + bw * 8) * 3;
    float px[24];
    {
        const float4* xin4 = (const float4*)(x + pix_off);
#pragma unroll
        for (int v = 0; v < 6; v++) {
            float4 q4 = xin4[v];
            px[v*4+0] = q4.x; px[v*4+1] = q4.y; px[v*4+2] = q4.z; px[v*4+3] = q4.w;
        }
    }

    // RGB -> YCbCr - 127  (biases: [-127, +1, +1])
    float yc0[8], yc1[8], yc2[8];
#pragma unroll
    for (int p = 0; p < 8; p++) {
        float R = 255.0f * px[3*p+0];
        float G = 255.0f * px[3*p+1];
        float Bv= 255.0f * px[3*p+2];
        yc0[p] = fmaf(0.299f,     R, fmaf( 0.587f,    G,  0.114f    * Bv)) - 127.0f;
        yc1[p] = fmaf(-0.168736f, R, fmaf(-0.331264f, G,  0.5f      * Bv)) + 1.0f;
        yc2[p] = fmaf(0.5f,       R, fmaf(-0.418688f, G, -0.081312f * Bv)) + 1.0f;
    }

    float ib0[8], ib1[8], ib2[8];

#pragma unroll
    for (int c = 0; c < 3; c++) {
        const float* qs = smq + (c ? 64 : 0);
        const float* rs = smr + (c ? 64 : 0);

        float a[8], o[8];
#pragma unroll
        for (int j = 0; j < 8; j++)
            a[j] = (c == 0) ? yc0[j] : ((c == 1) ? yc1[j] : yc2[j]);

        // S1: row transform (B * F^T)
        fdct8(a, o);

        // transpose 1
#pragma unroll
        for (int j = 0; j < 8; j++) sm[r * 9 + j] = o[j];
        __syncwarp();
#pragma unroll
        for (int j = 0; j < 8; j++) a[j] = sm[j * 9 + r];
        __syncwarp();

        // S2: column transform -> thread holds column r of X
        fdct8(a, o);

        // quantize + soft round (Q from smem, broadcast LDS)
#pragma unroll
        for (int j = 0; j < 8; j++) {
            float q  = qs[j * 8 + r];
            float rq = rs[j * 8 + r];
            float u  = o[j] * rq;
            a[j] = round_sin5(u) * q;
        }

        // store Xq column r
        {
            float* xqp = xq_out + ((size_t)((b * 3 + c) * 4096 + bh * 64 + bw) << 6) + r;
#pragma unroll
            for (int j = 0; j < 8; j++) xqp[j * 8] = a[j];
        }

        // S3: F^T * Xq (column-held)
        idct8(a, o);

        // transpose 2
#pragma unroll
        for (int j = 0; j < 8; j++) sm[r * 9 + j] = o[j];
        __syncwarp();
#pragma unroll
        for (int j = 0; j < 8; j++) a[j] = sm[j * 9 + r];
        __syncwarp();

        // S4: * F  -> thread holds row r of ib
        {
            float ot[8];
            idct8(a, ot);
#pragma unroll
            for (int l = 0; l < 8; l++) {
                if (c == 0) ib0[l] = ot[l];
                else if (c == 1) ib1[l] = ot[l];
                else ib2[l] = ot[l];
            }
        }
    }

    // YCbCr -> RGB, /255, clip
#pragma unroll
    for (int p = 0; p < 8; p++) {
        float Y  = ib0[p] + 127.0f;
        float Cb = ib1[p] + 127.0f;
        float Cr = ib2[p] + 127.0f;
        float R = fmaf(1.402f,  Cr, Y) + (-1.402f  * 128.0f);
        float G = fmaf(-0.344136f, Cb, fmaf(-0.714136f, Cr, Y)) + (1.058272f * 128.0f);
        float Bv= fmaf(1.772f,  Cb, Y) + (-1.772f  * 128.0f);
        px[3*p+0] = fminf(fmaxf(R * (1.0f/255.0f), 0.0f), 1.0f);
        px[3*p+1] = fminf(fmaxf(G * (1.0f/255.0f), 0.0f), 1.0f);
        px[3*p+2] = fminf(fmaxf(Bv * (1.0f/255.0f), 0.0f), 1.0f);
    }
    {
        float4* yo4 = (float4*)(y_out + pix_off);
#pragma unroll
        for (int v = 0; v < 6; v++) {
            float4 q4;
            q4.x = px[v*4+0]; q4.y = px[v*4+1]; q4.z = px[v*4+2]; q4.w = px[v*4+3];
            yo4[v] = q4;
        }
    }
}

extern "C" void kernel_launch(void* const* d_in, const int* in_sizes, int n_in,
                              void* d_out, int out_size)
{
    const float* x  = (const float*)d_in[0];
    const float* ql = (const float*)d_in[1];
    const float* qc = (const float*)d_in[2];

    float* y  = (float*)d_out;
    float* xq = (float*)d_out + (size_t)32 * 512 * 512 * 3;

    jpeg_kernel<<<4096, 256>>>(x, ql, qc, y, xq);
}

// round 4
// speedup vs baseline: 1.2979x; 1.0486x over previous
#include <cuda_runtime.h>

// DifferentiableJPEG on GB300:
//   x[32,512,512,3] fp32 -> y[32,512,512,3], Xq[32*3*4096,8,8]
// d_out = [ y | Xq ] fp32.
//
// 8 threads per 8x8 tile, one row each, 3 channels per thread.
// Even/odd DCT (36 ops), (q,1/q) float2 in smem, vectorized STS.128
// transposes (stride-12 rows / stride-104 tiles: conflict-free stores AND
// column reads), IDCT result overwrites channel input regs -> <=64 regs,
// 4 CTAs/SM.

static __device__ __forceinline__ float round_sin5(float u) {
    // u - sum_{k=1..5} ((-1)^{k+1}/(pi k)) sin(2 pi k u)
    float r  = u - rintf(u);                 // exact periodic reduction
    float a  = 6.283185307179586f * r;       // |a| <= pi
    float s1, c1;
    __sincosf(a, &s1, &c1);
    float tc = 2.0f * c1;
    float s2 = tc * s1;
    float s3 = fmaf(tc, s2, -s1);
    float s4 = fmaf(tc, s3, -s2);
    float s5 = fmaf(tc, s4, -s3);
    float S  = 0.3183098861837907f  * s1
             - 0.15915494309189535f * s2
             + 0.10610329539459689f * s3
             - 0.07957747154594767f * s4
             + 0.06366197723675814f * s5;
    return u - S;
}

// o[l] = sum_k a[k] * F[l][k]   (even/odd split)
static __device__ __forceinline__ void fdct8(const float a[8], float o[8]) {
    float e0 = a[0] + a[7], e1 = a[1] + a[6], e2 = a[2] + a[5], e3 = a[3] + a[4];
    float d0 = a[0] - a[7], d1 = a[1] - a[6], d2 = a[2] - a[5], d3 = a[3] - a[4];
    float g0 = e0 + e3, g1 = e1 + e2, g2 = e0 - e3, g3 = e1 - e2;
    o[0] = 0.3536f * (g0 + g1);
    o[4] = 0.3536f * (g0 - g1);
    o[2] = fmaf( 0.4619f, g2,  0.1913f * g3);
    o[6] = fmaf(-0.4619f, g3,  0.1913f * g2);
    o[1] = fmaf(0.4904f, d0, fmaf( 0.4157f, d1, fmaf( 0.2778f, d2,  0.0975f * d3)));
    o[3] = fmaf(0.4157f, d0, fmaf(-0.0975f, d1, fmaf(-0.4904f, d2, -0.2778f * d3)));
    o[5] = fmaf(0.2778f, d0, fmaf(-0.4904f, d1, fmaf( 0.0975f, d2,  0.4157f * d3)));
    o[7] = fmaf(0.0975f, d0, fmaf(-0.2778f, d1, fmaf( 0.4157f, d2, -0.4904f * d3)));
}

// o[l] = sum_k a[k] * F[k][l]   (even/odd split)
static __device__ __forceinline__ void idct8(const float a[8], float o[8]) {
    float t0 = 0.3536f * (a[0] + a[4]);
    float t1 = 0.3536f * (a[0] - a[4]);
    float u0 = fmaf(0.4619f, a[2],  0.1913f * a[6]);
    float u1 = fmaf(0.1913f, a[2], -0.4619f * a[6]);
    float E0 = t0 + u0, E1 = t1 + u1, E2 = t1 - u1, E3 = t0 - u0;
    float D0 = fmaf(0.4904f, a[1], fmaf( 0.4157f, a[3], fmaf( 0.2778f, a[5],  0.0975f * a[7])));
    float D1 = fmaf(0.4157f, a[1], fmaf(-0.0975f, a[3], fmaf(-0.4904f, a[5], -0.2778f * a[7])));
    float D2 = fmaf(0.2778f, a[1], fmaf(-0.4904f, a[3], fmaf( 0.0975f, a[5],  0.4157f * a[7])));
    float D3 = fmaf(0.0975f, a[1], fmaf(-0.2778f, a[3], fmaf( 0.4157f, a[5], -0.4904f * a[7])));
    o[0] = E0 + D0;  o[7] = E0 - D0;
    o[1] = E1 + D1;  o[6] = E1 - D1;
    o[2] = E2 + D2;  o[5] = E2 - D2;
    o[3] = E3 + D3;  o[4] = E3 - D3;
}

// transpose buffer geometry: row stride 12 floats (48B, 16B-aligned, bank
// starts 12r mod 32 partition banks into the 4-bank groups of STS.128
// quad-phases), tile stride 104 floats (8 banks shift per tile -> column
// reads (8t + r) hit all 32 banks exactly once).
#define TROW 12
#define TTILE 104

__global__ __launch_bounds__(256, 4)
void jpeg_kernel(const float* __restrict__ x,
                 const float* __restrict__ q_luma,
                 const float* __restrict__ q_chroma,
                 float* __restrict__ y_out,
                 float* __restrict__ xq_out)
{
    __shared__ __align__(16) float tb[32 * TTILE];
    __shared__ float2 smqr[128];   // [0:64) luma {q,1/q}, [64:128) chroma

    if (threadIdx.x < 128) {
        int c = threadIdx.x >> 6, i = threadIdx.x & 63;
        float q = c ? q_chroma[i] : q_luma[i];
        smqr[threadIdx.x] = make_float2(q, 1.0f / q);
    }
    __syncthreads();

    const int t  = threadIdx.x >> 3;          // tile within CTA
    const int r  = threadIdx.x & 7;           // row within tile
    const int tg = blockIdx.x * 32 + t;       // global tile id
    const int b   = tg >> 12;
    const int rem = tg & 4095;
    const int bh  = rem >> 6;
    const int bw  = rem & 63;

    float* sm = tb + t * TTILE;

    // load this row: 8 pixels x RGB = 24 contiguous floats
    const int pix_off = (((b * 512 + bh * 8 + r) * 512) + bw * 8) * 3;
    float px[24];
    {
        const float4* xin4 = (const float4*)(x + pix_off);
#pragma unroll
        for (int v = 0; v < 6; v++) {
            float4 q4 = xin4[v];
            px[v*4+0] = q4.x; px[v*4+1] = q4.y; px[v*4+2] = q4.z; px[v*4+3] = q4.w;
        }
    }

    // RGB -> YCbCr - 127  (biases: [-127, +1, +1]); px dies here
    float yc0[8], yc1[8], yc2[8];
#pragma unroll
    for (int p = 0; p < 8; p++) {
        float R = 255.0f * px[3*p+0];
        float G = 255.0f * px[3*p+1];
        float Bv= 255.0f * px[3*p+2];
        yc0[p] = fmaf(0.299f,     R, fmaf( 0.587f,    G,  0.114f    * Bv)) - 127.0f;
        yc1[p] = fmaf(-0.168736f, R, fmaf(-0.331264f, G,  0.5f      * Bv)) + 1.0f;
        yc2[p] = fmaf(0.5f,       R, fmaf(-0.418688f, G, -0.081312f * Bv)) + 1.0f;
    }

#pragma unroll
    for (int c = 0; c < 3; c++) {
        float* yc = (c == 0) ? yc0 : ((c == 1) ? yc1 : yc2);
        const float2* qr = smqr + (c ? 64 : 0);

        float a[8], o[8];
#pragma unroll
        for (int j = 0; j < 8; j++) a[j] = yc[j];

        // S1: row transform (B * F^T)
        fdct8(a, o);

        // transpose 1: vector row store, scalar column read
        {
            float4* sp = (float4*)(sm + r * TROW);
            sp[0] = make_float4(o[0], o[1], o[2], o[3]);
            sp[1] = make_float4(o[4], o[5], o[6], o[7]);
        }
        __syncwarp();
#pragma unroll
        for (int j = 0; j < 8; j++) a[j] = sm[j * TROW + r];
        __syncwarp();

        // S2: column transform -> thread holds column r of X
        fdct8(a, o);

        // quantize + soft round
#pragma unroll
        for (int j = 0; j < 8; j++) {
            float2 q2 = qr[j * 8 + r];
            float u   = o[j] * q2.y;
            a[j] = round_sin5(u) * q2.x;
        }

        // store Xq column r
        {
            float* xqp = xq_out + ((size_t)((b * 3 + c) * 4096 + bh * 64 + bw) << 6) + r;
#pragma unroll
            for (int j = 0; j < 8; j++) xqp[j * 8] = a[j];
        }

        // S3: F^T * Xq (column-held)
        idct8(a, o);

        // transpose 2
        {
            float4* sp = (float4*)(sm + r * TROW);
            sp[0] = make_float4(o[0], o[1], o[2], o[3]);
            sp[1] = make_float4(o[4], o[5], o[6], o[7]);
        }
        __syncwarp();
#pragma unroll
        for (int j = 0; j < 8; j++) a[j] = sm[j * TROW + r];
        __syncwarp();

        // S4: * F -> thread holds row r of ib; overwrite channel input regs
        idct8(a, o);
#pragma unroll
        for (int l = 0; l < 8; l++) yc[l] = o[l];
    }

    // YCbCr -> RGB, /255, clip  (yc* now hold ib*)
#pragma unroll
    for (int p = 0; p < 8; p++) {
        float Y  = yc0[p] + 127.0f;
        float Cb = yc1[p] + 127.0f;
        float Cr = yc2[p] + 127.0f;
        float R = fmaf(1.402f,  Cr, Y) + (-1.402f  * 128.0f);
        float G = fmaf(-0.344136f, Cb, fmaf(-0.714136f, Cr, Y)) + (1.058272f * 128.0f);
        float Bv= fmaf(1.772f,  Cb, Y) + (-1.772f  * 128.0f);
        px[3*p+0] = fminf(fmaxf(R * (1.0f/255.0f), 0.0f), 1.0f);
        px[3*p+1] = fminf(fmaxf(G * (1.0f/255.0f), 0.0f), 1.0f);
        px[3*p+2] = fminf(fmaxf(Bv * (1.0f/255.0f), 0.0f), 1.0f);
    }
    {
        float4* yo4 = (float4*)(y_out + pix_off);
#pragma unroll
        for (int v = 0; v < 6; v++) {
            float4 q4;
            q4.x = px[v*4+0]; q4.y = px[v*4+1]; q4.z = px[v*4+2]; q4.w = px[v*4+3];
            yo4[v] = q4;
        }
    }
}

extern "C" void kernel_launch(void* const* d_in, const int* in_sizes, int n_in,
                              void* d_out, int out_size)
{
    const float* x  = (const float*)d_in[0];
    const float* ql = (const float*)d_in[1];
    const float* qc = (const float*)d_in[2];

    float* y  = (float*)d_out;
    float* xq = (float*)d_out + (size_t)32 * 512 * 512 * 3;

    jpeg_kernel<<<4096, 256>>>(x, ql, qc, y, xq);
}